// round 14
// baseline (speedup 1.0000x reference)
#include <cuda_runtime.h>
#include <cuda_bf16.h>
#include <cuda_fp16.h>
#include <math.h>
#include <stdint.h>

#define B_  4
#define S_  2048
#define D_  1024
#define H_  16
#define HD_ 64
#define M_  (B_ * S_)     // 8192
#define NC_ 16            // GEMM K chunks of 64 (K = 1024)
#define NIT (S_ / 64)     // attention key tiles = 32

// ---------------- scratch (static device memory) ---------------------------
__device__ __half g_A2[M_ * D_];           // fp16 activations (x, then attn out)
__device__ __half g_W2[4 * D_ * D_];       // fp16 weights (q,k,v,o)
__device__ __half g_Qh[M_ * D_];
__device__ __half g_Kh[M_ * D_];
__device__ __half g_Vth[M_ * D_];          // V transposed [b][h][d][s]
__device__ float g_u[M_];
__device__ float g_lam[B_];
__device__ float g_pmrm[S_];

// ---------------- helpers ----------------------------------------------------
__device__ __forceinline__ uint32_t smem_u32(const void* p) {
    uint32_t a;
    asm("{ .reg .u64 t; cvta.to.shared.u64 t, %1; cvt.u32.u64 %0, t; }" : "=r"(a) : "l"(p));
    return a;
}
__device__ __forceinline__ void ldsm4(uint32_t& r0, uint32_t& r1, uint32_t& r2, uint32_t& r3,
                                      uint32_t addr) {
    asm volatile("ldmatrix.sync.aligned.m8n8.x4.shared.b16 {%0,%1,%2,%3}, [%4];"
                 : "=r"(r0), "=r"(r1), "=r"(r2), "=r"(r3) : "r"(addr));
}
__device__ __forceinline__ void mma_f16(float* c, const uint32_t* a, uint32_t b0, uint32_t b1) {
    asm volatile("mma.sync.aligned.m16n8k16.row.col.f32.f16.f16.f32 "
                 "{%0,%1,%2,%3}, {%4,%5,%6,%7}, {%8,%9}, {%0,%1,%2,%3};"
                 : "+f"(c[0]), "+f"(c[1]), "+f"(c[2]), "+f"(c[3])
                 : "r"(a[0]), "r"(a[1]), "r"(a[2]), "r"(a[3]), "r"(b0), "r"(b1));
}
#define CP_ASYNC16(sm, gm) \
    asm volatile("cp.async.cg.shared.global [%0], [%1], 16;" :: "r"(sm), "l"(gm))
#define CP_COMMIT() asm volatile("cp.async.commit_group;")
#define CP_WAIT1()  asm volatile("cp.async.wait_group 1;")
#define CP_WAIT0()  asm volatile("cp.async.wait_group 0;")

__device__ __forceinline__ uint32_t pk_f16(float lo, float hi) {
    uint32_t d;
    asm("cvt.rn.f16x2.f32 %0, %1, %2;" : "=r"(d) : "f"(hi), "f"(lo));
    return d;
}
__device__ __forceinline__ float ex2(float x) {
    float y; asm("ex2.approx.ftz.f32 %0, %1;" : "=f"(y) : "f"(x)); return y;
}

// ---------------- fused prologue: fp16 convert x + weights, row_u, pmrm ------
__global__ void __launch_bounds__(256) prologue(const float* __restrict__ x,
                                                const float* __restrict__ dx,
                                                const float* __restrict__ pm,
                                                const float* __restrict__ wq,
                                                const float* __restrict__ wk,
                                                const float* __restrict__ wv,
                                                const float* __restrict__ wo)
{
    __shared__ float shx[32], shd[32];
    const int rg = blockIdx.x;
    const int lane = threadIdx.x & 31, wid = threadIdx.x >> 5;

    if (rg >= M_ + 4 * D_) {                 // ---- pmrm ----
        const int q = rg - M_ - 4 * D_;
        float s = 0.f;
        for (int k = threadIdx.x; k < S_; k += 256) s += pm[(size_t)q * S_ + k];
        #pragma unroll
        for (int o = 16; o; o >>= 1) s += __shfl_xor_sync(0xffffffffu, s, o);
        if (lane == 0) shx[wid] = s;
        __syncthreads();
        if (wid == 0) {
            s = (lane < 8) ? shx[lane] : 0.f;
            #pragma unroll
            for (int o = 4; o; o >>= 1) s += __shfl_xor_sync(0xffffffffu, s, o);
            if (lane == 0) g_pmrm[q] = s / (float)S_;
        }
        return;
    }

    const int c = threadIdx.x * 4;
    if (rg < M_) {
        const float* src = x + (size_t)rg * D_;
        float4 v = *(const float4*)(src + c);
        __half2 hA = {__float2half_rn(v.x), __float2half_rn(v.y)};
        __half2 hB = {__float2half_rn(v.z), __float2half_rn(v.w)};
        __half* d0 = g_A2 + (size_t)rg * D_ + c;
        *(__half2*)(d0)     = hA;
        *(__half2*)(d0 + 2) = hB;
        // row_u
        float4 dv = *(const float4*)(dx + (size_t)rg * D_ + c);
        float sx = v.x*v.x + v.y*v.y + v.z*v.z + v.w*v.w;
        float sd = dv.x*dv.x + dv.y*dv.y + dv.z*dv.z + dv.w*dv.w;
        #pragma unroll
        for (int o = 16; o; o >>= 1) {
            sx += __shfl_xor_sync(0xffffffffu, sx, o);
            sd += __shfl_xor_sync(0xffffffffu, sd, o);
        }
        if (lane == 0) { shx[wid] = sx; shd[wid] = sd; }
        __syncthreads();
        if (wid == 0) {
            sx = (lane < 8) ? shx[lane] : 0.f;
            sd = (lane < 8) ? shd[lane] : 0.f;
            #pragma unroll
            for (int o = 4; o; o >>= 1) {
                sx += __shfl_xor_sync(0xffffffffu, sx, o);
                sd += __shfl_xor_sync(0xffffffffu, sd, o);
            }
            if (lane == 0) g_u[rg] = sqrtf(sd) / (sqrtf(sx) + 1e-8f);
        }
    } else {
        int idx = rg - M_;
        int j = idx >> 10;
        int row = idx & 1023;
        const float* w = (j == 0) ? wq : (j == 1) ? wk : (j == 2) ? wv : wo;
        const float* src = w + (size_t)row * D_;
        float4 v = *(const float4*)(src + c);
        __half2 hA = {__float2half_rn(v.x), __float2half_rn(v.y)};
        __half2 hB = {__float2half_rn(v.z), __float2half_rn(v.w)};
        __half* d0 = g_W2 + ((size_t)j * D_ + row) * D_ + c;
        *(__half2*)(d0)     = hA;
        *(__half2*)(d0 + 2) = hB;
    }
}

__global__ void __launch_bounds__(256) lam_kernel()
{
    const int b = blockIdx.x;
    float s = 0.f;
    for (int i = threadIdx.x; i < S_; i += 256) s += g_u[b * S_ + i];
    __shared__ float sh[32];
    int lane = threadIdx.x & 31, wid = threadIdx.x >> 5;
    #pragma unroll
    for (int o = 16; o; o >>= 1) s += __shfl_xor_sync(0xffffffffu, s, o);
    if (lane == 0) sh[wid] = s;
    __syncthreads();
    if (wid == 0) {
        s = (lane < 8) ? sh[lane] : 0.f;
        #pragma unroll
        for (int o = 4; o; o >>= 1) s += __shfl_xor_sync(0xffffffffu, s, o);
        if (lane == 0) g_lam[b] = 10.0f * expf(-5.0f * (s / (float)S_));
    }
}

// ---------------- HMMA GEMM (3-stage cp.async pipeline, fp16, K=1024) ---------
#define GST 16384
#define GT_TOT (6 * GST)

template<int EPI>
__global__ void __launch_bounds__(256, 2) gemm_mma(const __half* __restrict__ A2,
                                                   const __half* __restrict__ W2,
                                                   const float* __restrict__ b0,
                                                   const float* __restrict__ b1,
                                                   const float* __restrict__ b2,
                                                   float* __restrict__ cout)
{
    extern __shared__ char smem[];
    const uint32_t sA = smem_u32(smem);
    const uint32_t sB = sA + 3 * GST;

    const int t    = threadIdx.x;
    const int lane = t & 31;
    const int w    = t >> 5;
    const int z    = blockIdx.x >> 3;
    const float* bias = (z == 0) ? b0 : (z == 1) ? b1 : b2;

    const int wm = (w & 3) * 32;
    const int wn = (w >> 2) * 64;

    const int ch   = t & 7;
    const int rb   = t >> 3;
    const int swch = ch ^ (rb & 7);
    const __half* gAp[4];
    const __half* gBp[4];
    uint32_t smA[4], smB[4];
    #pragma unroll
    for (int p = 0; p < 4; p++) {
        int row = rb + p * 32;
        gAp[p] = A2 + ((size_t)blockIdx.y * 128 + row) * D_ + ch * 8;
        gBp[p] = W2 + ((size_t)blockIdx.x * 128 + row) * D_ + ch * 8;
        smA[p] = sA + row * 128 + swch * 16;
        smB[p] = sB + row * 128 + swch * 16;
    }

    auto load_chunk = [&](int kc, int st) {
        const size_t goff = (size_t)kc * 64;
        #pragma unroll
        for (int p = 0; p < 4; p++) {
            CP_ASYNC16(smA[p] + st * GST, gAp[p] + goff);
            CP_ASYNC16(smB[p] + st * GST, gBp[p] + goff);
        }
    };

    float acc[2][8][4];
    #pragma unroll
    for (int i = 0; i < 2; i++)
        #pragma unroll
        for (int j = 0; j < 8; j++)
            #pragma unroll
            for (int k = 0; k < 4; k++) acc[i][j][k] = 0.f;

    load_chunk(0, 0); CP_COMMIT();
    load_chunk(1, 1); CP_COMMIT();

    const int lrow = lane & 15;
    const int lhalf = lane >> 4;

    int st = 0;
    for (int kc = 0; kc < NC_; kc++) {
        CP_WAIT1();
        __syncthreads();
        if (kc + 2 < NC_) {
            int ns = st + 2; if (ns >= 3) ns -= 3;
            load_chunk(kc + 2, ns);
        }
        CP_COMMIT();

        const uint32_t bA = sA + st * GST;
        const uint32_t bB = sB + st * GST;

        #pragma unroll
        for (int ks = 0; ks < 4; ks++) {
            uint32_t af[2][4];
            #pragma unroll
            for (int mi = 0; mi < 2; mi++) {
                int row = wm + mi * 16 + lrow;
                int chk = (ks * 2 + lhalf) ^ (row & 7);
                ldsm4(af[mi][0], af[mi][1], af[mi][2], af[mi][3],
                      bA + row * 128 + chk * 16);
            }
            #pragma unroll
            for (int nj = 0; nj < 4; nj++) {
                uint32_t r0, r1, r2, r3;
                int row = wn + nj * 16 + lrow;
                int chk = (ks * 2 + lhalf) ^ (row & 7);
                ldsm4(r0, r1, r2, r3, bB + row * 128 + chk * 16);
                #pragma unroll
                for (int mi = 0; mi < 2; mi++) {
                    mma_f16(acc[mi][nj * 2 + 0], af[mi], r0, r2);
                    mma_f16(acc[mi][nj * 2 + 1], af[mi], r1, r3);
                }
            }
        }
        if (++st == 3) st = 0;
    }

    const int tr = lane >> 2;
    const int tc = (lane & 3) * 2;
    const int gy = blockIdx.y * 128;
    const int gxz = (blockIdx.x & 7) * 128;

    if (EPI == 0) {
        #pragma unroll
        for (int mi = 0; mi < 2; mi++)
            #pragma unroll
            for (int nj = 0; nj < 8; nj++) {
                int col = gxz + wn + nj * 8 + tc;
                float2 bv = *(const float2*)(bias + col);
                int row0 = gy + wm + mi * 16 + tr;
                float2 o0 = { acc[mi][nj][0] + bv.x, acc[mi][nj][1] + bv.y };
                float2 o1 = { acc[mi][nj][2] + bv.x, acc[mi][nj][3] + bv.y };
                *(float2*)(cout + (size_t)row0 * D_ + col)       = o0;
                *(float2*)(cout + (size_t)(row0 + 8) * D_ + col) = o1;
            }
    } else {
        #pragma unroll
        for (int mi = 0; mi < 2; mi++)
            #pragma unroll
            for (int nj = 0; nj < 8; nj++) {
                int col = gxz + wn + nj * 8 + tc;
                float2 bv = *(const float2*)(bias + col);
                #pragma unroll
                for (int rr = 0; rr < 2; rr++) {
                    int row = gy + wm + mi * 16 + tr + rr * 8;
                    float v0 = acc[mi][nj][rr * 2 + 0] + bv.x;
                    float v1 = acc[mi][nj][rr * 2 + 1] + bv.y;
                    __half h0 = __float2half_rn(v0);
                    __half h1 = __float2half_rn(v1);
                    if (z == 0) {
                        __half2 hp = {h0, h1};
                        *(__half2*)(g_Qh + (size_t)row * D_ + col) = hp;
                    } else if (z == 1) {
                        __half2 hp = {h0, h1};
                        *(__half2*)(g_Kh + (size_t)row * D_ + col) = hp;
                    } else {                    // V transposed
                        int bb = row >> 11, s = row & 2047;
                        int hh = col >> 6, dl = col & 63;
                        size_t base = ((size_t)(bb * H_ + hh) * 64 + dl) * S_ + s;
                        g_Vth[base] = h0;
                        g_Vth[base + S_] = h1;
                    }
                }
            }
    }
}

// ---------------- HMMA flash attention (128 thr, m32/warp, shared K/V frags) --
#define AS_Q   0           // 128 x 128B = 16384
#define AS_KV  16384       // + buf*16384: [Kh 8K][Vh 8K], 3 buffers
#define AS_BUF 16384
#define AS_TOT (16384 + 3 * 16384)   // 65536

__global__ void __launch_bounds__(128, 3) attn_mma(const float* __restrict__ pm,
                                                   __half* __restrict__ A2out)
{
    extern __shared__ char smem[];
    const uint32_t base = smem_u32(smem);
    const int b = blockIdx.z, h = blockIdx.y, qt = blockIdx.x;
    const int t = threadIdx.x;          // 0..127
    const int lane = t & 31;
    const int w = t >> 5;               // 0..3, warp owns q-rows [w*32, w*32+32)
    const float lamv  = g_lam[b];
    const bool doclip = (lamv > 1.0f);
    const float LOG2E = 1.44269504f;
    const float lam2  = lamv * LOG2E;
    const float sc2   = 0.125f * LOG2E;

    // Q tile: 128 rows x 128B = 1024 16B-chunks, 8 per thread
    #pragma unroll
    for (int i = 0; i < 8; i++) {
        int cid = t + i * 128;
        int r = cid >> 3, ch = cid & 7;
        size_t go = ((size_t)(b * S_ + qt * 128 + r)) * D_ + h * HD_ + ch * 8;
        uint32_t so = base + AS_Q + r * 128 + ((ch ^ (r & 7)) * 16);
        CP_ASYNC16(so, g_Qh + go);
    }
    auto load_kv = [&](int kt, int buf) {
        uint32_t sb = base + AS_KV + buf * AS_BUF;
        #pragma unroll
        for (int i = 0; i < 4; i++) {
            int cid = t + i * 128;      // 0..511
            int r = cid >> 3, ch = cid & 7;
            uint32_t sw = (ch ^ (r & 7)) * 16;
            size_t gk = ((size_t)(b * S_ + kt * 64 + r)) * D_ + h * HD_ + ch * 8;
            size_t gv = ((size_t)((b * H_ + h) * 64 + r)) * S_ + kt * 64 + ch * 8;
            uint32_t so = sb + r * 128 + sw;
            CP_ASYNC16(so,        g_Kh + gk);
            CP_ASYNC16(so + 8192, g_Vth + gv);
        }
    };
    load_kv(0, 0);
    CP_COMMIT();
    load_kv(1, 1);
    CP_COMMIT();

    const int lrow = lane & 15;
    const int lhalf = lane >> 4;
    const int tr = lane >> 2;
    const int tc = (lane & 3) * 2;
    const int qrow0 = qt * 128 + w * 32 + tr;   // mi=0 rows; mi=1 adds 16

    float m[2][2], l[2][2], thr[2][2];
    #pragma unroll
    for (int mi = 0; mi < 2; mi++)
        #pragma unroll
        for (int rr = 0; rr < 2; rr++) {
            m[mi][rr] = -1e30f; l[mi][rr] = 0.f;
            thr[mi][rr] = lam2 * g_pmrm[qrow0 + mi * 16 + rr * 8];
        }

    float oacc[2][8][4];
    #pragma unroll
    for (int mi = 0; mi < 2; mi++)
        #pragma unroll
        for (int j = 0; j < 8; j++)
            #pragma unroll
            for (int k = 0; k < 4; k++) oacc[mi][j][k] = 0.f;

    const float* pmbase = pm + (size_t)qrow0 * S_ + tc;
    const int arow = w * 32 + lrow;

    int buf = 0;
    for (int kt = 0; kt < NIT; kt++) {
        CP_WAIT1();
        __syncthreads();
        if (kt + 2 < NIT) {
            int nb = buf + 2; if (nb >= 3) nb -= 3;
            load_kv(kt + 2, nb);
        }
        CP_COMMIT();

        const uint32_t bK = base + AS_KV + buf * AS_BUF;
        const uint32_t bV = bK + 8192;

        float acc[2][8][4];
        #pragma unroll
        for (int mi = 0; mi < 2; mi++)
            #pragma unroll
            for (int j = 0; j < 8; j++)
                #pragma unroll
                for (int k = 0; k < 4; k++) acc[mi][j][k] = 0.f;

        // ---- S = Q*K (K fragment shared across both mi) ----
        #pragma unroll
        for (int ks = 0; ks < 4; ks++) {
            uint32_t af[2][4];
            #pragma unroll
            for (int mi = 0; mi < 2; mi++) {
                int row = arow + mi * 16;
                int chk = ((ks * 2 + lhalf) ^ (row & 7)) * 16;
                ldsm4(af[mi][0], af[mi][1], af[mi][2], af[mi][3],
                      base + AS_Q + row * 128 + chk);
            }
            #pragma unroll
            for (int nj = 0; nj < 4; nj++) {
                int brow = nj * 16 + lrow;
                int bchk = ((ks * 2 + lhalf) ^ (brow & 7)) * 16;
                uint32_t kh0, kh1, kh2, kh3;
                ldsm4(kh0, kh1, kh2, kh3, bK + brow * 128 + bchk);
                #pragma unroll
                for (int mi = 0; mi < 2; mi++) {
                    mma_f16(acc[mi][nj * 2],     af[mi], kh0, kh2);
                    mma_f16(acc[mi][nj * 2 + 1], af[mi], kh1, kh3);
                }
            }
        }

        // ---- bias + clip + online softmax (log2 domain, per mi; pm inline) ----
        #pragma unroll
        for (int mi = 0; mi < 2; mi++) {
            const float* pmr0 = pmbase + (size_t)(mi * 16) * S_ + kt * 64;
            const float* pmr1 = pmr0 + (size_t)8 * S_;
            float mx0 = -1e30f, mx1 = -1e30f;
            #pragma unroll
            for (int nt = 0; nt < 8; nt++) {
                float2 p0 = *(const float2*)(pmr0 + nt * 8);
                float2 p1 = *(const float2*)(pmr1 + nt * 8);
                float L;
                L = fmaf(lam2, p0.x, acc[mi][nt][0] * sc2);
                if (doclip && L < thr[mi][0]) L = -1e30f;
                acc[mi][nt][0] = L; mx0 = fmaxf(mx0, L);
                L = fmaf(lam2, p0.y, acc[mi][nt][1] * sc2);
                if (doclip && L < thr[mi][0]) L = -1e30f;
                acc[mi][nt][1] = L; mx0 = fmaxf(mx0, L);
                L = fmaf(lam2, p1.x, acc[mi][nt][2] * sc2);
                if (doclip && L < thr[mi][1]) L = -1e30f;
                acc[mi][nt][2] = L; mx1 = fmaxf(mx1, L);
                L = fmaf(lam2, p1.y, acc[mi][nt][3] * sc2);
                if (doclip && L < thr[mi][1]) L = -1e30f;
                acc[mi][nt][3] = L; mx1 = fmaxf(mx1, L);
            }
            mx0 = fmaxf(mx0, __shfl_xor_sync(0xffffffffu, mx0, 1));
            mx0 = fmaxf(mx0, __shfl_xor_sync(0xffffffffu, mx0, 2));
            mx1 = fmaxf(mx1, __shfl_xor_sync(0xffffffffu, mx1, 1));
            mx1 = fmaxf(mx1, __shfl_xor_sync(0xffffffffu, mx1, 2));
            float mn0 = fmaxf(m[mi][0], mx0), mn1 = fmaxf(m[mi][1], mx1);
            float rs0 = ex2(m[mi][0] - mn0), rs1 = ex2(m[mi][1] - mn1);
            float s0 = 0.f, s1 = 0.f;
            #pragma unroll
            for (int nt = 0; nt < 8; nt++) {
                float p;
                p = ex2(acc[mi][nt][0] - mn0); acc[mi][nt][0] = p; s0 += p;
                p = ex2(acc[mi][nt][1] - mn0); acc[mi][nt][1] = p; s0 += p;
                p = ex2(acc[mi][nt][2] - mn1); acc[mi][nt][2] = p; s1 += p;
                p = ex2(acc[mi][nt][3] - mn1); acc[mi][nt][3] = p; s1 += p;
            }
            s0 += __shfl_xor_sync(0xffffffffu, s0, 1);
            s0 += __shfl_xor_sync(0xffffffffu, s0, 2);
            s1 += __shfl_xor_sync(0xffffffffu, s1, 1);
            s1 += __shfl_xor_sync(0xffffffffu, s1, 2);
            l[mi][0] = fmaf(l[mi][0], rs0, s0); m[mi][0] = mn0;
            l[mi][1] = fmaf(l[mi][1], rs1, s1); m[mi][1] = mn1;
            #pragma unroll
            for (int nt = 0; nt < 8; nt++) {
                oacc[mi][nt][0] *= rs0; oacc[mi][nt][1] *= rs0;
                oacc[mi][nt][2] *= rs1; oacc[mi][nt][3] *= rs1;
            }
        }

        // ---- O += P*V (V fragment shared across both mi) ----
        #pragma unroll
        for (int ks = 0; ks < 4; ks++) {
            const int na = 2 * ks, nb2 = 2 * ks + 1;
            uint32_t aph[2][4];
            #pragma unroll
            for (int mi = 0; mi < 2; mi++) {
                aph[mi][0] = pk_f16(acc[mi][na][0],  acc[mi][na][1]);
                aph[mi][1] = pk_f16(acc[mi][na][2],  acc[mi][na][3]);
                aph[mi][2] = pk_f16(acc[mi][nb2][0], acc[mi][nb2][1]);
                aph[mi][3] = pk_f16(acc[mi][nb2][2], acc[mi][nb2][3]);
            }
            #pragma unroll
            for (int nj = 0; nj < 4; nj++) {
                int brow = nj * 16 + lrow;
                int bchk = ((ks * 2 + lhalf) ^ (brow & 7)) * 16;
                uint32_t vh0, vh1, vh2, vh3;
                ldsm4(vh0, vh1, vh2, vh3, bV + brow * 128 + bchk);
                #pragma unroll
                for (int mi = 0; mi < 2; mi++) {
                    mma_f16(oacc[mi][nj * 2],     aph[mi], vh0, vh2);
                    mma_f16(oacc[mi][nj * 2 + 1], aph[mi], vh1, vh3);
                }
            }
        }

        if (++buf == 3) buf = 0;
    }

    // ---- epilogue: normalize and write fp16 O into A2 ----
    #pragma unroll
    for (int mi = 0; mi < 2; mi++) {
        const float inv0 = 1.0f / l[mi][0], inv1 = 1.0f / l[mi][1];
        const size_t row0 = (size_t)(b * S_) + qt * 128 + w * 32 + mi * 16 + tr;
        #pragma unroll
        for (int nt = 0; nt < 8; nt++) {
            int col = h * HD_ + nt * 8 + tc;
            #pragma unroll
            for (int rr = 0; rr < 2; rr++) {
                float v0 = oacc[mi][nt][rr * 2 + 0] * (rr ? inv1 : inv0);
                float v1 = oacc[mi][nt][rr * 2 + 1] * (rr ? inv1 : inv0);
                __half2 hp = {__float2half_rn(v0), __float2half_rn(v1)};
                *(__half2*)(A2out + (row0 + rr * 8) * D_ + col) = hp;
            }
        }
    }
}

// ---------------- launch ------------------------------------------------------
extern "C" void kernel_launch(void* const* d_in, const int* in_sizes, int n_in,
                              void* d_out, int out_size)
{
    const float* x  = (const float*)d_in[0];
    const float* pm = (const float*)d_in[1];
    const float* dx = (const float*)d_in[2];
    const float* wq = (const float*)d_in[3];
    const float* bq = (const float*)d_in[4];
    const float* wk = (const float*)d_in[5];
    const float* bk = (const float*)d_in[6];
    const float* wv = (const float*)d_in[7];
    const float* bv = (const float*)d_in[8];
    const float* wo = (const float*)d_in[9];
    const float* bo = (const float*)d_in[10];
    float* out = (float*)d_out;

    __half *gA2, *gW2;
    cudaGetSymbolAddress((void**)&gA2, g_A2);
    cudaGetSymbolAddress((void**)&gW2, g_W2);

    cudaFuncSetAttribute(gemm_mma<0>, cudaFuncAttributeMaxDynamicSharedMemorySize, GT_TOT);
    cudaFuncSetAttribute(gemm_mma<1>, cudaFuncAttributeMaxDynamicSharedMemorySize, GT_TOT);
    cudaFuncSetAttribute(attn_mma, cudaFuncAttributeMaxDynamicSharedMemorySize, AS_TOT);

    // fused prologue: fp16 converts + row_u + pmrm, then lam
    prologue<<<M_ + 4 * D_ + S_, 256>>>(x, dx, pm, wq, wk, wv, wo);
    lam_kernel<<<B_, 256>>>();

    // fused QKV projection: single GEMM, N = 3072 (q|k|v stacked), K = 1024
    dim3 gqkv(3 * D_ / 128, M_ / 128);
    gemm_mma<1><<<gqkv, 256, GT_TOT>>>(gA2, gW2, bq, bk, bv, nullptr);

    // HMMA flash attention (128 threads, m32/warp) -> writes fp16 O into A2
    dim3 ag(S_ / 128, H_, B_);
    attn_mma<<<ag, 128, AS_TOT>>>(pm, gA2);

    // output projection (K = 1024)
    dim3 go(D_ / 128, M_ / 128);
    gemm_mma<0><<<go, 256, GT_TOT>>>(gA2, gW2 + 3 * (size_t)D_ * D_, bo, bo, bo, out);
}

// round 15
// speedup vs baseline: 1.3344x; 1.3344x over previous
#include <cuda_runtime.h>
#include <cuda_bf16.h>
#include <cuda_fp16.h>
#include <math.h>
#include <stdint.h>

#define B_  4
#define S_  2048
#define D_  1024
#define H_  16
#define HD_ 64
#define M_  (B_ * S_)     // 8192
#define NC_ 16            // GEMM K chunks of 64 (K = 1024)
#define NIT (S_ / 64)     // attention key tiles = 32

// ---------------- scratch (static device memory) ---------------------------
__device__ __half g_A2[M_ * D_];           // fp16 activations (x, then attn out)
__device__ __half g_W2[4 * D_ * D_];       // fp16 weights (q,k,v,o)
__device__ __half g_Qh[M_ * D_];
__device__ __half g_Kh[M_ * D_];
__device__ __half g_Vth[M_ * D_];          // V transposed [b][h][d][s]
__device__ float g_u[M_];
__device__ float g_lam[B_];
__device__ float g_pmrm[S_];

// ---------------- helpers ----------------------------------------------------
__device__ __forceinline__ uint32_t smem_u32(const void* p) {
    uint32_t a;
    asm("{ .reg .u64 t; cvta.to.shared.u64 t, %1; cvt.u32.u64 %0, t; }" : "=r"(a) : "l"(p));
    return a;
}
__device__ __forceinline__ void ldsm4(uint32_t& r0, uint32_t& r1, uint32_t& r2, uint32_t& r3,
                                      uint32_t addr) {
    asm volatile("ldmatrix.sync.aligned.m8n8.x4.shared.b16 {%0,%1,%2,%3}, [%4];"
                 : "=r"(r0), "=r"(r1), "=r"(r2), "=r"(r3) : "r"(addr));
}
__device__ __forceinline__ void mma_f16(float* c, const uint32_t* a, uint32_t b0, uint32_t b1) {
    asm volatile("mma.sync.aligned.m16n8k16.row.col.f32.f16.f16.f32 "
                 "{%0,%1,%2,%3}, {%4,%5,%6,%7}, {%8,%9}, {%0,%1,%2,%3};"
                 : "+f"(c[0]), "+f"(c[1]), "+f"(c[2]), "+f"(c[3])
                 : "r"(a[0]), "r"(a[1]), "r"(a[2]), "r"(a[3]), "r"(b0), "r"(b1));
}
#define CP_ASYNC16(sm, gm) \
    asm volatile("cp.async.cg.shared.global [%0], [%1], 16;" :: "r"(sm), "l"(gm))
#define CP_COMMIT() asm volatile("cp.async.commit_group;")
#define CP_WAIT1()  asm volatile("cp.async.wait_group 1;")
#define CP_WAIT2()  asm volatile("cp.async.wait_group 2;")

__device__ __forceinline__ uint32_t pk_f16(float lo, float hi) {
    uint32_t d;
    asm("cvt.rn.f16x2.f32 %0, %1, %2;" : "=r"(d) : "f"(hi), "f"(lo));
    return d;
}
__device__ __forceinline__ float ex2(float x) {
    float y; asm("ex2.approx.ftz.f32 %0, %1;" : "=f"(y) : "f"(x)); return y;
}

// ---------------- fused prologue: fp16 convert x + weights, row_u, pmrm ------
__global__ void __launch_bounds__(256) prologue(const float* __restrict__ x,
                                                const float* __restrict__ dx,
                                                const float* __restrict__ pm,
                                                const float* __restrict__ wq,
                                                const float* __restrict__ wk,
                                                const float* __restrict__ wv,
                                                const float* __restrict__ wo)
{
    __shared__ float shx[32], shd[32];
    const int rg = blockIdx.x;
    const int lane = threadIdx.x & 31, wid = threadIdx.x >> 5;

    if (rg >= M_ + 4 * D_) {                 // ---- pmrm ----
        const int q = rg - M_ - 4 * D_;
        float s = 0.f;
        for (int k = threadIdx.x; k < S_; k += 256) s += pm[(size_t)q * S_ + k];
        #pragma unroll
        for (int o = 16; o; o >>= 1) s += __shfl_xor_sync(0xffffffffu, s, o);
        if (lane == 0) shx[wid] = s;
        __syncthreads();
        if (wid == 0) {
            s = (lane < 8) ? shx[lane] : 0.f;
            #pragma unroll
            for (int o = 4; o; o >>= 1) s += __shfl_xor_sync(0xffffffffu, s, o);
            if (lane == 0) g_pmrm[q] = s / (float)S_;
        }
        return;
    }

    const int c = threadIdx.x * 4;
    if (rg < M_) {
        const float* src = x + (size_t)rg * D_;
        float4 v = *(const float4*)(src + c);
        __half2 hA = {__float2half_rn(v.x), __float2half_rn(v.y)};
        __half2 hB = {__float2half_rn(v.z), __float2half_rn(v.w)};
        __half* d0 = g_A2 + (size_t)rg * D_ + c;
        *(__half2*)(d0)     = hA;
        *(__half2*)(d0 + 2) = hB;
        // row_u
        float4 dv = *(const float4*)(dx + (size_t)rg * D_ + c);
        float sx = v.x*v.x + v.y*v.y + v.z*v.z + v.w*v.w;
        float sd = dv.x*dv.x + dv.y*dv.y + dv.z*dv.z + dv.w*dv.w;
        #pragma unroll
        for (int o = 16; o; o >>= 1) {
            sx += __shfl_xor_sync(0xffffffffu, sx, o);
            sd += __shfl_xor_sync(0xffffffffu, sd, o);
        }
        if (lane == 0) { shx[wid] = sx; shd[wid] = sd; }
        __syncthreads();
        if (wid == 0) {
            sx = (lane < 8) ? shx[lane] : 0.f;
            sd = (lane < 8) ? shd[lane] : 0.f;
            #pragma unroll
            for (int o = 4; o; o >>= 1) {
                sx += __shfl_xor_sync(0xffffffffu, sx, o);
                sd += __shfl_xor_sync(0xffffffffu, sd, o);
            }
            if (lane == 0) g_u[rg] = sqrtf(sd) / (sqrtf(sx) + 1e-8f);
        }
    } else {
        int idx = rg - M_;
        int j = idx >> 10;
        int row = idx & 1023;
        const float* w = (j == 0) ? wq : (j == 1) ? wk : (j == 2) ? wv : wo;
        const float* src = w + (size_t)row * D_;
        float4 v = *(const float4*)(src + c);
        __half2 hA = {__float2half_rn(v.x), __float2half_rn(v.y)};
        __half2 hB = {__float2half_rn(v.z), __float2half_rn(v.w)};
        __half* d0 = g_W2 + ((size_t)j * D_ + row) * D_ + c;
        *(__half2*)(d0)     = hA;
        *(__half2*)(d0 + 2) = hB;
    }
}

__global__ void __launch_bounds__(256) lam_kernel()
{
    const int b = blockIdx.x;
    float s = 0.f;
    for (int i = threadIdx.x; i < S_; i += 256) s += g_u[b * S_ + i];
    __shared__ float sh[32];
    int lane = threadIdx.x & 31, wid = threadIdx.x >> 5;
    #pragma unroll
    for (int o = 16; o; o >>= 1) s += __shfl_xor_sync(0xffffffffu, s, o);
    if (lane == 0) sh[wid] = s;
    __syncthreads();
    if (wid == 0) {
        s = (lane < 8) ? sh[lane] : 0.f;
        #pragma unroll
        for (int o = 4; o; o >>= 1) s += __shfl_xor_sync(0xffffffffu, s, o);
        if (lane == 0) g_lam[b] = 10.0f * expf(-5.0f * (s / (float)S_));
    }
}

// ---------------- HMMA GEMM (3-stage cp.async pipeline, fp16, K=1024) ---------
#define GST 16384
#define GT_TOT (6 * GST)

template<int EPI>
__global__ void __launch_bounds__(256, 2) gemm_mma(const __half* __restrict__ A2,
                                                   const __half* __restrict__ W2,
                                                   const float* __restrict__ b0,
                                                   const float* __restrict__ b1,
                                                   const float* __restrict__ b2,
                                                   float* __restrict__ cout)
{
    extern __shared__ char smem[];
    const uint32_t sA = smem_u32(smem);
    const uint32_t sB = sA + 3 * GST;

    const int t    = threadIdx.x;
    const int lane = t & 31;
    const int w    = t >> 5;
    const int z    = blockIdx.x >> 3;
    const float* bias = (z == 0) ? b0 : (z == 1) ? b1 : b2;

    const int wm = (w & 3) * 32;
    const int wn = (w >> 2) * 64;

    const int ch   = t & 7;
    const int rb   = t >> 3;
    const int swch = ch ^ (rb & 7);
    const __half* gAp[4];
    const __half* gBp[4];
    uint32_t smA[4], smB[4];
    #pragma unroll
    for (int p = 0; p < 4; p++) {
        int row = rb + p * 32;
        gAp[p] = A2 + ((size_t)blockIdx.y * 128 + row) * D_ + ch * 8;
        gBp[p] = W2 + ((size_t)blockIdx.x * 128 + row) * D_ + ch * 8;
        smA[p] = sA + row * 128 + swch * 16;
        smB[p] = sB + row * 128 + swch * 16;
    }

    auto load_chunk = [&](int kc, int st) {
        const size_t goff = (size_t)kc * 64;
        #pragma unroll
        for (int p = 0; p < 4; p++) {
            CP_ASYNC16(smA[p] + st * GST, gAp[p] + goff);
            CP_ASYNC16(smB[p] + st * GST, gBp[p] + goff);
        }
    };

    float acc[2][8][4];
    #pragma unroll
    for (int i = 0; i < 2; i++)
        #pragma unroll
        for (int j = 0; j < 8; j++)
            #pragma unroll
            for (int k = 0; k < 4; k++) acc[i][j][k] = 0.f;

    load_chunk(0, 0); CP_COMMIT();
    load_chunk(1, 1); CP_COMMIT();

    const int lrow = lane & 15;
    const int lhalf = lane >> 4;

    int st = 0;
    for (int kc = 0; kc < NC_; kc++) {
        CP_WAIT1();
        __syncthreads();
        if (kc + 2 < NC_) {
            int ns = st + 2; if (ns >= 3) ns -= 3;
            load_chunk(kc + 2, ns);
        }
        CP_COMMIT();

        const uint32_t bA = sA + st * GST;
        const uint32_t bB = sB + st * GST;

        #pragma unroll
        for (int ks = 0; ks < 4; ks++) {
            uint32_t af[2][4];
            #pragma unroll
            for (int mi = 0; mi < 2; mi++) {
                int row = wm + mi * 16 + lrow;
                int chk = (ks * 2 + lhalf) ^ (row & 7);
                ldsm4(af[mi][0], af[mi][1], af[mi][2], af[mi][3],
                      bA + row * 128 + chk * 16);
            }
            #pragma unroll
            for (int nj = 0; nj < 4; nj++) {
                uint32_t r0, r1, r2, r3;
                int row = wn + nj * 16 + lrow;
                int chk = (ks * 2 + lhalf) ^ (row & 7);
                ldsm4(r0, r1, r2, r3, bB + row * 128 + chk * 16);
                #pragma unroll
                for (int mi = 0; mi < 2; mi++) {
                    mma_f16(acc[mi][nj * 2 + 0], af[mi], r0, r2);
                    mma_f16(acc[mi][nj * 2 + 1], af[mi], r1, r3);
                }
            }
        }
        if (++st == 3) st = 0;
    }

    const int tr = lane >> 2;
    const int tc = (lane & 3) * 2;
    const int gy = blockIdx.y * 128;
    const int gxz = (blockIdx.x & 7) * 128;

    if (EPI == 0) {
        #pragma unroll
        for (int mi = 0; mi < 2; mi++)
            #pragma unroll
            for (int nj = 0; nj < 8; nj++) {
                int col = gxz + wn + nj * 8 + tc;
                float2 bv = *(const float2*)(bias + col);
                int row0 = gy + wm + mi * 16 + tr;
                float2 o0 = { acc[mi][nj][0] + bv.x, acc[mi][nj][1] + bv.y };
                float2 o1 = { acc[mi][nj][2] + bv.x, acc[mi][nj][3] + bv.y };
                *(float2*)(cout + (size_t)row0 * D_ + col)       = o0;
                *(float2*)(cout + (size_t)(row0 + 8) * D_ + col) = o1;
            }
    } else {
        #pragma unroll
        for (int mi = 0; mi < 2; mi++)
            #pragma unroll
            for (int nj = 0; nj < 8; nj++) {
                int col = gxz + wn + nj * 8 + tc;
                float2 bv = *(const float2*)(bias + col);
                #pragma unroll
                for (int rr = 0; rr < 2; rr++) {
                    int row = gy + wm + mi * 16 + tr + rr * 8;
                    float v0 = acc[mi][nj][rr * 2 + 0] + bv.x;
                    float v1 = acc[mi][nj][rr * 2 + 1] + bv.y;
                    __half h0 = __float2half_rn(v0);
                    __half h1 = __float2half_rn(v1);
                    if (z == 0) {
                        __half2 hp = {h0, h1};
                        *(__half2*)(g_Qh + (size_t)row * D_ + col) = hp;
                    } else if (z == 1) {
                        __half2 hp = {h0, h1};
                        *(__half2*)(g_Kh + (size_t)row * D_ + col) = hp;
                    } else {                    // V transposed
                        int bb = row >> 11, s = row & 2047;
                        int hh = col >> 6, dl = col & 63;
                        size_t base = ((size_t)(bb * H_ + hh) * 64 + dl) * S_ + s;
                        g_Vth[base] = h0;
                        g_Vth[base + S_] = h1;
                    }
                }
            }
    }
}

// ---------------- HMMA flash attention (4-buffer pipeline, log2 softmax) ------
#define AS_Q   0           // 128 x 128B = 16384
#define AS_KV  16384       // + buf*16384: [Kh 8K][Vh 8K], 4 buffers
#define AS_BUF 16384
#define AS_TOT (16384 + 4 * 16384)   // 81920

__global__ void __launch_bounds__(256, 2) attn_mma(const float* __restrict__ pm,
                                                   __half* __restrict__ A2out)
{
    extern __shared__ char smem[];
    const uint32_t base = smem_u32(smem);
    const int b = blockIdx.z, h = blockIdx.y, qt = blockIdx.x;
    const int t = threadIdx.x;
    const int lane = t & 31;
    const int w = t >> 5;
    const float lamv  = g_lam[b];
    const bool doclip = (lamv > 1.0f);
    const float LOG2E = 1.44269504f;
    const float lam2  = lamv * LOG2E;
    const float sc2   = 0.125f * LOG2E;

    // Q tile: 128 rows x 128B (group 0, with kv0)
    #pragma unroll
    for (int i = 0; i < 4; i++) {
        int cid = t + i * 256;             // 0..1023
        int r = cid >> 3, ch = cid & 7;
        size_t go = ((size_t)(b * S_ + qt * 128 + r)) * D_ + h * HD_ + ch * 8;
        uint32_t so = base + AS_Q + r * 128 + ((ch ^ (r & 7)) * 16);
        CP_ASYNC16(so, g_Qh + go);
    }
    auto load_kv = [&](int kt, int buf) {
        uint32_t sb = base + AS_KV + buf * AS_BUF;
        #pragma unroll
        for (int i = 0; i < 2; i++) {
            int cid = t + i * 256;
            int r = cid >> 3, ch = cid & 7;
            uint32_t sw = (ch ^ (r & 7)) * 16;
            size_t gk = ((size_t)(b * S_ + kt * 64 + r)) * D_ + h * HD_ + ch * 8;
            size_t gv = ((size_t)((b * H_ + h) * 64 + r)) * S_ + kt * 64 + ch * 8;
            uint32_t so = sb + r * 128 + sw;
            CP_ASYNC16(so,        g_Kh + gk);
            CP_ASYNC16(so + 8192, g_Vth + gv);
        }
    };
    load_kv(0, 0);
    CP_COMMIT();       // group 0: Q + kv0
    load_kv(1, 1);
    CP_COMMIT();       // group 1: kv1
    load_kv(2, 2);
    CP_COMMIT();       // group 2: kv2

    const int lrow = lane & 15;
    const int lhalf = lane >> 4;
    const int tr = lane >> 2;
    const int tc = (lane & 3) * 2;
    const int qrow0 = qt * 128 + w * 16 + tr;
    const float thr0 = lam2 * g_pmrm[qrow0];
    const float thr1 = lam2 * g_pmrm[qrow0 + 8];

    float m0 = -1e30f, m1 = -1e30f, l0 = 0.f, l1 = 0.f;
    float oacc[8][4];
    #pragma unroll
    for (int j = 0; j < 8; j++)
        #pragma unroll
        for (int k = 0; k < 4; k++) oacc[j][k] = 0.f;

    const float* pmr0 = pm + (size_t)qrow0 * S_ + tc;
    const float* pmr1 = pmr0 + (size_t)8 * S_;
    const int arow = w * 16 + lrow;

    for (int kt = 0; kt < NIT; kt++) {
        CP_WAIT2();                  // group kt complete; kt+1, kt+2 may fly
        __syncthreads();
        // buffer (kt+3)%4 == (kt-1)%4 is free after this barrier
        if (kt + 3 < NIT) load_kv(kt + 3, (kt + 3) & 3);
        CP_COMMIT();

        const int buf = kt & 3;
        const uint32_t bK = base + AS_KV + buf * AS_BUF;
        const uint32_t bV = bK + 8192;

        float2 pmv0[8], pmv1[8];
        #pragma unroll
        for (int nt = 0; nt < 8; nt++) {
            pmv0[nt] = *(const float2*)(pmr0 + kt * 64 + nt * 8);
            pmv1[nt] = *(const float2*)(pmr1 + kt * 64 + nt * 8);
        }

        float acc[8][4];
        #pragma unroll
        for (int j = 0; j < 8; j++)
            #pragma unroll
            for (int k = 0; k < 4; k++) acc[j][k] = 0.f;

        // ---- S = Q*K ----
        #pragma unroll
        for (int ks = 0; ks < 4; ks++) {
            uint32_t ah[4];
            int achk = ((ks * 2 + lhalf) ^ (arow & 7)) * 16;
            ldsm4(ah[0], ah[1], ah[2], ah[3], base + AS_Q + arow * 128 + achk);
            #pragma unroll
            for (int nj = 0; nj < 4; nj++) {
                int brow = nj * 16 + lrow;
                int bchk = ((ks * 2 + lhalf) ^ (brow & 7)) * 16;
                uint32_t kh0, kh1, kh2, kh3;
                ldsm4(kh0, kh1, kh2, kh3, bK + brow * 128 + bchk);
                mma_f16(acc[nj * 2],     ah, kh0, kh2);
                mma_f16(acc[nj * 2 + 1], ah, kh1, kh3);
            }
        }

        // ---- bias + clip + online softmax (log2 domain) ----
        float mx0 = -1e30f, mx1 = -1e30f;
        #pragma unroll
        for (int nt = 0; nt < 8; nt++) {
            float L;
            L = fmaf(lam2, pmv0[nt].x, acc[nt][0] * sc2);
            if (doclip && L < thr0) L = -1e30f;
            acc[nt][0] = L; mx0 = fmaxf(mx0, L);
            L = fmaf(lam2, pmv0[nt].y, acc[nt][1] * sc2);
            if (doclip && L < thr0) L = -1e30f;
            acc[nt][1] = L; mx0 = fmaxf(mx0, L);
            L = fmaf(lam2, pmv1[nt].x, acc[nt][2] * sc2);
            if (doclip && L < thr1) L = -1e30f;
            acc[nt][2] = L; mx1 = fmaxf(mx1, L);
            L = fmaf(lam2, pmv1[nt].y, acc[nt][3] * sc2);
            if (doclip && L < thr1) L = -1e30f;
            acc[nt][3] = L; mx1 = fmaxf(mx1, L);
        }
        mx0 = fmaxf(mx0, __shfl_xor_sync(0xffffffffu, mx0, 1));
        mx0 = fmaxf(mx0, __shfl_xor_sync(0xffffffffu, mx0, 2));
        mx1 = fmaxf(mx1, __shfl_xor_sync(0xffffffffu, mx1, 1));
        mx1 = fmaxf(mx1, __shfl_xor_sync(0xffffffffu, mx1, 2));
        float mn0 = fmaxf(m0, mx0), mn1 = fmaxf(m1, mx1);
        float rs0 = ex2(m0 - mn0), rs1 = ex2(m1 - mn1);
        float s0 = 0.f, s1 = 0.f;
        #pragma unroll
        for (int nt = 0; nt < 8; nt++) {
            float p;
            p = ex2(acc[nt][0] - mn0); acc[nt][0] = p; s0 += p;
            p = ex2(acc[nt][1] - mn0); acc[nt][1] = p; s0 += p;
            p = ex2(acc[nt][2] - mn1); acc[nt][2] = p; s1 += p;
            p = ex2(acc[nt][3] - mn1); acc[nt][3] = p; s1 += p;
        }
        s0 += __shfl_xor_sync(0xffffffffu, s0, 1);
        s0 += __shfl_xor_sync(0xffffffffu, s0, 2);
        s1 += __shfl_xor_sync(0xffffffffu, s1, 1);
        s1 += __shfl_xor_sync(0xffffffffu, s1, 2);
        l0 = fmaf(l0, rs0, s0); m0 = mn0;
        l1 = fmaf(l1, rs1, s1); m1 = mn1;
        #pragma unroll
        for (int nt = 0; nt < 8; nt++) {
            oacc[nt][0] *= rs0; oacc[nt][1] *= rs0;
            oacc[nt][2] *= rs1; oacc[nt][3] *= rs1;
        }

        // ---- O += P*V ----
        #pragma unroll
        for (int ks = 0; ks < 4; ks++) {
            const int na = 2 * ks, nb2 = 2 * ks + 1;
            uint32_t aph[4];
            aph[0] = pk_f16(acc[na][0],  acc[na][1]);
            aph[1] = pk_f16(acc[na][2],  acc[na][3]);
            aph[2] = pk_f16(acc[nb2][0], acc[nb2][1]);
            aph[3] = pk_f16(acc[nb2][2], acc[nb2][3]);
            #pragma unroll
            for (int nj = 0; nj < 4; nj++) {
                int brow = nj * 16 + lrow;
                int bchk = ((ks * 2 + lhalf) ^ (brow & 7)) * 16;
                uint32_t vh0, vh1, vh2, vh3;
                ldsm4(vh0, vh1, vh2, vh3, bV + brow * 128 + bchk);
                mma_f16(oacc[nj * 2],     aph, vh0, vh2);
                mma_f16(oacc[nj * 2 + 1], aph, vh1, vh3);
            }
        }
    }

    // ---- epilogue: normalize and write fp16 O into A2 ----
    const float inv0 = 1.0f / l0, inv1 = 1.0f / l1;
    const size_t row0 = (size_t)(b * S_) + qt * 128 + w * 16 + tr;
    #pragma unroll
    for (int nt = 0; nt < 8; nt++) {
        int col = h * HD_ + nt * 8 + tc;
        #pragma unroll
        for (int rr = 0; rr < 2; rr++) {
            float v0 = oacc[nt][rr * 2 + 0] * (rr ? inv1 : inv0);
            float v1 = oacc[nt][rr * 2 + 1] * (rr ? inv1 : inv0);
            __half2 hp = {__float2half_rn(v0), __float2half_rn(v1)};
            *(__half2*)(A2out + (row0 + rr * 8) * D_ + col) = hp;
        }
    }
}

// ---------------- launch ------------------------------------------------------
extern "C" void kernel_launch(void* const* d_in, const int* in_sizes, int n_in,
                              void* d_out, int out_size)
{
    const float* x  = (const float*)d_in[0];
    const float* pm = (const float*)d_in[1];
    const float* dx = (const float*)d_in[2];
    const float* wq = (const float*)d_in[3];
    const float* bq = (const float*)d_in[4];
    const float* wk = (const float*)d_in[5];
    const float* bk = (const float*)d_in[6];
    const float* wv = (const float*)d_in[7];
    const float* bv = (const float*)d_in[8];
    const float* wo = (const float*)d_in[9];
    const float* bo = (const float*)d_in[10];
    float* out = (float*)d_out;

    __half *gA2, *gW2;
    cudaGetSymbolAddress((void**)&gA2, g_A2);
    cudaGetSymbolAddress((void**)&gW2, g_W2);

    cudaFuncSetAttribute(gemm_mma<0>, cudaFuncAttributeMaxDynamicSharedMemorySize, GT_TOT);
    cudaFuncSetAttribute(gemm_mma<1>, cudaFuncAttributeMaxDynamicSharedMemorySize, GT_TOT);
    cudaFuncSetAttribute(attn_mma, cudaFuncAttributeMaxDynamicSharedMemorySize, AS_TOT);

    // fused prologue: fp16 converts + row_u + pmrm, then lam
    prologue<<<M_ + 4 * D_ + S_, 256>>>(x, dx, pm, wq, wk, wv, wo);
    lam_kernel<<<B_, 256>>>();

    // fused QKV projection: single GEMM, N = 3072 (q|k|v stacked), K = 1024
    dim3 gqkv(3 * D_ / 128, M_ / 128);
    gemm_mma<1><<<gqkv, 256, GT_TOT>>>(gA2, gW2, bq, bk, bv, nullptr);

    // HMMA flash attention (4-buffer pipeline) -> writes fp16 O into A2
    dim3 ag(S_ / 128, H_, B_);
    attn_mma<<<ag, 256, AS_TOT>>>(pm, gA2);

    // output projection (K = 1024)
    dim3 go(D_ / 128, M_ / 128);
    gemm_mma<0><<<go, 256, GT_TOT>>>(gA2, gW2 + 3 * (size_t)D_ * D_, bo, bo, bo, out);
}

// round 16
// speedup vs baseline: 1.3407x; 1.0047x over previous
#include <cuda_runtime.h>
#include <cuda_bf16.h>
#include <cuda_fp16.h>
#include <math.h>
#include <stdint.h>

#define B_  4
#define S_  2048
#define D_  1024
#define H_  16
#define HD_ 64
#define M_  (B_ * S_)     // 8192
#define NC_ 16            // GEMM K chunks of 64 (K = 1024)
#define NIT (S_ / 64)     // attention key tiles = 32

// ---------------- scratch (static device memory) ---------------------------
__device__ __half g_A2[M_ * D_];           // fp16 activations (x, then attn out)
__device__ __half g_W2[4 * D_ * D_];       // fp16 weights (q,k,v,o)
__device__ __half g_Qh[M_ * D_];
__device__ __half g_Kh[M_ * D_];
__device__ __half g_V[M_ * D_];            // V row-major [b*S + s][D] (like K)
__device__ float g_u[M_];
__device__ float g_lam[B_];
__device__ float g_pmrm[S_];

// ---------------- helpers ----------------------------------------------------
__device__ __forceinline__ uint32_t smem_u32(const void* p) {
    uint32_t a;
    asm("{ .reg .u64 t; cvta.to.shared.u64 t, %1; cvt.u32.u64 %0, t; }" : "=r"(a) : "l"(p));
    return a;
}
__device__ __forceinline__ void ldsm4(uint32_t& r0, uint32_t& r1, uint32_t& r2, uint32_t& r3,
                                      uint32_t addr) {
    asm volatile("ldmatrix.sync.aligned.m8n8.x4.shared.b16 {%0,%1,%2,%3}, [%4];"
                 : "=r"(r0), "=r"(r1), "=r"(r2), "=r"(r3) : "r"(addr));
}
__device__ __forceinline__ void ldsm4t(uint32_t& r0, uint32_t& r1, uint32_t& r2, uint32_t& r3,
                                       uint32_t addr) {
    asm volatile("ldmatrix.sync.aligned.m8n8.x4.trans.shared.b16 {%0,%1,%2,%3}, [%4];"
                 : "=r"(r0), "=r"(r1), "=r"(r2), "=r"(r3) : "r"(addr));
}
__device__ __forceinline__ void mma_f16(float* c, const uint32_t* a, uint32_t b0, uint32_t b1) {
    asm volatile("mma.sync.aligned.m16n8k16.row.col.f32.f16.f16.f32 "
                 "{%0,%1,%2,%3}, {%4,%5,%6,%7}, {%8,%9}, {%0,%1,%2,%3};"
                 : "+f"(c[0]), "+f"(c[1]), "+f"(c[2]), "+f"(c[3])
                 : "r"(a[0]), "r"(a[1]), "r"(a[2]), "r"(a[3]), "r"(b0), "r"(b1));
}
#define CP_ASYNC16(sm, gm) \
    asm volatile("cp.async.cg.shared.global [%0], [%1], 16;" :: "r"(sm), "l"(gm))
#define CP_COMMIT() asm volatile("cp.async.commit_group;")
#define CP_WAIT1()  asm volatile("cp.async.wait_group 1;")
#define CP_WAIT2()  asm volatile("cp.async.wait_group 2;")

__device__ __forceinline__ uint32_t pk_f16(float lo, float hi) {
    uint32_t d;
    asm("cvt.rn.f16x2.f32 %0, %1, %2;" : "=r"(d) : "f"(hi), "f"(lo));
    return d;
}
__device__ __forceinline__ float ex2(float x) {
    float y; asm("ex2.approx.ftz.f32 %0, %1;" : "=f"(y) : "f"(x)); return y;
}

// ---------------- fused prologue: fp16 convert x + weights, row_u, pmrm ------
__global__ void __launch_bounds__(256) prologue(const float* __restrict__ x,
                                                const float* __restrict__ dx,
                                                const float* __restrict__ pm,
                                                const float* __restrict__ wq,
                                                const float* __restrict__ wk,
                                                const float* __restrict__ wv,
                                                const float* __restrict__ wo)
{
    __shared__ float shx[32], shd[32];
    const int rg = blockIdx.x;
    const int lane = threadIdx.x & 31, wid = threadIdx.x >> 5;

    if (rg >= M_ + 4 * D_) {                 // ---- pmrm ----
        const int q = rg - M_ - 4 * D_;
        float s = 0.f;
        for (int k = threadIdx.x; k < S_; k += 256) s += pm[(size_t)q * S_ + k];
        #pragma unroll
        for (int o = 16; o; o >>= 1) s += __shfl_xor_sync(0xffffffffu, s, o);
        if (lane == 0) shx[wid] = s;
        __syncthreads();
        if (wid == 0) {
            s = (lane < 8) ? shx[lane] : 0.f;
            #pragma unroll
            for (int o = 4; o; o >>= 1) s += __shfl_xor_sync(0xffffffffu, s, o);
            if (lane == 0) g_pmrm[q] = s / (float)S_;
        }
        return;
    }

    const int c = threadIdx.x * 4;
    if (rg < M_) {
        const float* src = x + (size_t)rg * D_;
        float4 v = *(const float4*)(src + c);
        __half2 hA = {__float2half_rn(v.x), __float2half_rn(v.y)};
        __half2 hB = {__float2half_rn(v.z), __float2half_rn(v.w)};
        __half* d0 = g_A2 + (size_t)rg * D_ + c;
        *(__half2*)(d0)     = hA;
        *(__half2*)(d0 + 2) = hB;
        // row_u
        float4 dv = *(const float4*)(dx + (size_t)rg * D_ + c);
        float sx = v.x*v.x + v.y*v.y + v.z*v.z + v.w*v.w;
        float sd = dv.x*dv.x + dv.y*dv.y + dv.z*dv.z + dv.w*dv.w;
        #pragma unroll
        for (int o = 16; o; o >>= 1) {
            sx += __shfl_xor_sync(0xffffffffu, sx, o);
            sd += __shfl_xor_sync(0xffffffffu, sd, o);
        }
        if (lane == 0) { shx[wid] = sx; shd[wid] = sd; }
        __syncthreads();
        if (wid == 0) {
            sx = (lane < 8) ? shx[lane] : 0.f;
            sd = (lane < 8) ? shd[lane] : 0.f;
            #pragma unroll
            for (int o = 4; o; o >>= 1) {
                sx += __shfl_xor_sync(0xffffffffu, sx, o);
                sd += __shfl_xor_sync(0xffffffffu, sd, o);
            }
            if (lane == 0) g_u[rg] = sqrtf(sd) / (sqrtf(sx) + 1e-8f);
        }
    } else {
        int idx = rg - M_;
        int j = idx >> 10;
        int row = idx & 1023;
        const float* w = (j == 0) ? wq : (j == 1) ? wk : (j == 2) ? wv : wo;
        const float* src = w + (size_t)row * D_;
        float4 v = *(const float4*)(src + c);
        __half2 hA = {__float2half_rn(v.x), __float2half_rn(v.y)};
        __half2 hB = {__float2half_rn(v.z), __float2half_rn(v.w)};
        __half* d0 = g_W2 + ((size_t)j * D_ + row) * D_ + c;
        *(__half2*)(d0)     = hA;
        *(__half2*)(d0 + 2) = hB;
    }
}

__global__ void __launch_bounds__(256) lam_kernel()
{
    const int b = blockIdx.x;
    float s = 0.f;
    for (int i = threadIdx.x; i < S_; i += 256) s += g_u[b * S_ + i];
    __shared__ float sh[32];
    int lane = threadIdx.x & 31, wid = threadIdx.x >> 5;
    #pragma unroll
    for (int o = 16; o; o >>= 1) s += __shfl_xor_sync(0xffffffffu, s, o);
    if (lane == 0) sh[wid] = s;
    __syncthreads();
    if (wid == 0) {
        s = (lane < 8) ? sh[lane] : 0.f;
        #pragma unroll
        for (int o = 4; o; o >>= 1) s += __shfl_xor_sync(0xffffffffu, s, o);
        if (lane == 0) g_lam[b] = 10.0f * expf(-5.0f * (s / (float)S_));
    }
}

// ---------------- HMMA GEMM (3-stage cp.async pipeline, fp16, K=1024) ---------
#define GST 16384
#define GT_TOT (6 * GST)

template<int EPI>
__global__ void __launch_bounds__(256, 2) gemm_mma(const __half* __restrict__ A2,
                                                   const __half* __restrict__ W2,
                                                   const float* __restrict__ b0,
                                                   const float* __restrict__ b1,
                                                   const float* __restrict__ b2,
                                                   float* __restrict__ cout)
{
    extern __shared__ char smem[];
    const uint32_t sA = smem_u32(smem);
    const uint32_t sB = sA + 3 * GST;

    const int t    = threadIdx.x;
    const int lane = t & 31;
    const int w    = t >> 5;
    const int z    = blockIdx.x >> 3;
    const float* bias = (z == 0) ? b0 : (z == 1) ? b1 : b2;

    const int wm = (w & 3) * 32;
    const int wn = (w >> 2) * 64;

    const int ch   = t & 7;
    const int rb   = t >> 3;
    const int swch = ch ^ (rb & 7);
    const __half* gAp[4];
    const __half* gBp[4];
    uint32_t smA[4], smB[4];
    #pragma unroll
    for (int p = 0; p < 4; p++) {
        int row = rb + p * 32;
        gAp[p] = A2 + ((size_t)blockIdx.y * 128 + row) * D_ + ch * 8;
        gBp[p] = W2 + ((size_t)blockIdx.x * 128 + row) * D_ + ch * 8;
        smA[p] = sA + row * 128 + swch * 16;
        smB[p] = sB + row * 128 + swch * 16;
    }

    auto load_chunk = [&](int kc, int st) {
        const size_t goff = (size_t)kc * 64;
        #pragma unroll
        for (int p = 0; p < 4; p++) {
            CP_ASYNC16(smA[p] + st * GST, gAp[p] + goff);
            CP_ASYNC16(smB[p] + st * GST, gBp[p] + goff);
        }
    };

    float acc[2][8][4];
    #pragma unroll
    for (int i = 0; i < 2; i++)
        #pragma unroll
        for (int j = 0; j < 8; j++)
            #pragma unroll
            for (int k = 0; k < 4; k++) acc[i][j][k] = 0.f;

    load_chunk(0, 0); CP_COMMIT();
    load_chunk(1, 1); CP_COMMIT();

    const int lrow = lane & 15;
    const int lhalf = lane >> 4;

    int st = 0;
    for (int kc = 0; kc < NC_; kc++) {
        CP_WAIT1();
        __syncthreads();
        if (kc + 2 < NC_) {
            int ns = st + 2; if (ns >= 3) ns -= 3;
            load_chunk(kc + 2, ns);
        }
        CP_COMMIT();

        const uint32_t bA = sA + st * GST;
        const uint32_t bB = sB + st * GST;

        #pragma unroll
        for (int ks = 0; ks < 4; ks++) {
            uint32_t af[2][4];
            #pragma unroll
            for (int mi = 0; mi < 2; mi++) {
                int row = wm + mi * 16 + lrow;
                int chk = (ks * 2 + lhalf) ^ (row & 7);
                ldsm4(af[mi][0], af[mi][1], af[mi][2], af[mi][3],
                      bA + row * 128 + chk * 16);
            }
            #pragma unroll
            for (int nj = 0; nj < 4; nj++) {
                uint32_t r0, r1, r2, r3;
                int row = wn + nj * 16 + lrow;
                int chk = (ks * 2 + lhalf) ^ (row & 7);
                ldsm4(r0, r1, r2, r3, bB + row * 128 + chk * 16);
                #pragma unroll
                for (int mi = 0; mi < 2; mi++) {
                    mma_f16(acc[mi][nj * 2 + 0], af[mi], r0, r2);
                    mma_f16(acc[mi][nj * 2 + 1], af[mi], r1, r3);
                }
            }
        }
        if (++st == 3) st = 0;
    }

    const int tr = lane >> 2;
    const int tc = (lane & 3) * 2;
    const int gy = blockIdx.y * 128;
    const int gxz = (blockIdx.x & 7) * 128;

    if (EPI == 0) {
        #pragma unroll
        for (int mi = 0; mi < 2; mi++)
            #pragma unroll
            for (int nj = 0; nj < 8; nj++) {
                int col = gxz + wn + nj * 8 + tc;
                float2 bv = *(const float2*)(bias + col);
                int row0 = gy + wm + mi * 16 + tr;
                float2 o0 = { acc[mi][nj][0] + bv.x, acc[mi][nj][1] + bv.y };
                float2 o1 = { acc[mi][nj][2] + bv.x, acc[mi][nj][3] + bv.y };
                *(float2*)(cout + (size_t)row0 * D_ + col)       = o0;
                *(float2*)(cout + (size_t)(row0 + 8) * D_ + col) = o1;
            }
    } else {
        __half* outp = (z == 0) ? g_Qh : (z == 1) ? g_Kh : g_V;
        #pragma unroll
        for (int mi = 0; mi < 2; mi++)
            #pragma unroll
            for (int nj = 0; nj < 8; nj++) {
                int col = gxz + wn + nj * 8 + tc;
                float2 bv = *(const float2*)(bias + col);
                #pragma unroll
                for (int rr = 0; rr < 2; rr++) {
                    int row = gy + wm + mi * 16 + tr + rr * 8;
                    float v0 = acc[mi][nj][rr * 2 + 0] + bv.x;
                    float v1 = acc[mi][nj][rr * 2 + 1] + bv.y;
                    __half2 hp = {__float2half_rn(v0), __float2half_rn(v1)};
                    *(__half2*)(outp + (size_t)row * D_ + col) = hp;
                }
            }
    }
}

// ---------------- HMMA flash attention (4-buf pipeline, ldsm.trans V) ---------
#define AS_Q   0           // 128 x 128B = 16384
#define AS_KV  16384       // + buf*16384: [Kh 8K][V 8K], 4 buffers
#define AS_BUF 16384
#define AS_TOT (16384 + 4 * 16384)   // 81920

__global__ void __launch_bounds__(256, 2) attn_mma(const float* __restrict__ pm,
                                                   __half* __restrict__ A2out)
{
    extern __shared__ char smem[];
    const uint32_t base = smem_u32(smem);
    const int b = blockIdx.z, h = blockIdx.y, qt = blockIdx.x;
    const int t = threadIdx.x;
    const int lane = t & 31;
    const int w = t >> 5;
    const float lamv  = g_lam[b];
    const bool doclip = (lamv > 1.0f);
    const float LOG2E = 1.44269504f;
    const float lam2  = lamv * LOG2E;
    const float sc2   = 0.125f * LOG2E;

    // Q tile: 128 rows x 128B (group 0, with kv0)
    #pragma unroll
    for (int i = 0; i < 4; i++) {
        int cid = t + i * 256;             // 0..1023
        int r = cid >> 3, ch = cid & 7;
        size_t go = ((size_t)(b * S_ + qt * 128 + r)) * D_ + h * HD_ + ch * 8;
        uint32_t so = base + AS_Q + r * 128 + ((ch ^ (r & 7)) * 16);
        CP_ASYNC16(so, g_Qh + go);
    }
    // K and V both row-major [s][d]: identical addressing
    auto load_kv = [&](int kt, int buf) {
        uint32_t sb = base + AS_KV + buf * AS_BUF;
        #pragma unroll
        for (int i = 0; i < 2; i++) {
            int cid = t + i * 256;
            int r = cid >> 3, ch = cid & 7;
            uint32_t sw = (ch ^ (r & 7)) * 16;
            size_t gk = ((size_t)(b * S_ + kt * 64 + r)) * D_ + h * HD_ + ch * 8;
            uint32_t so = sb + r * 128 + sw;
            CP_ASYNC16(so,        g_Kh + gk);
            CP_ASYNC16(so + 8192, g_V + gk);
        }
    };
    load_kv(0, 0);
    CP_COMMIT();       // group 0: Q + kv0
    load_kv(1, 1);
    CP_COMMIT();       // group 1: kv1
    load_kv(2, 2);
    CP_COMMIT();       // group 2: kv2

    const int lrow = lane & 15;
    const int lhalf = lane >> 4;
    const int tr = lane >> 2;
    const int tc = (lane & 3) * 2;
    const int qrow0 = qt * 128 + w * 16 + tr;
    const float thr0 = lam2 * g_pmrm[qrow0];
    const float thr1 = lam2 * g_pmrm[qrow0 + 8];

    // ldsm.trans lane addressing for V [s][d]:
    // lanes 0-7:(k0-7,c0) 8-15:(k0-7,c1) 16-23:(k8-15,c0) 24-31:(k8-15,c1)
    const int vkrow = (lane & 7) + ((lane >> 4) << 3);   // s-row offset within 16
    const int vcolh = (lane >> 3) & 1;                   // 16B column half

    float m0 = -1e30f, m1 = -1e30f, l0 = 0.f, l1 = 0.f;
    float oacc[8][4];
    #pragma unroll
    for (int j = 0; j < 8; j++)
        #pragma unroll
        for (int k = 0; k < 4; k++) oacc[j][k] = 0.f;

    const float* pmr0 = pm + (size_t)qrow0 * S_ + tc;
    const float* pmr1 = pmr0 + (size_t)8 * S_;
    const int arow = w * 16 + lrow;

    for (int kt = 0; kt < NIT; kt++) {
        CP_WAIT2();
        __syncthreads();
        if (kt + 3 < NIT) load_kv(kt + 3, (kt + 3) & 3);
        CP_COMMIT();

        const int buf = kt & 3;
        const uint32_t bK = base + AS_KV + buf * AS_BUF;
        const uint32_t bV = bK + 8192;

        float2 pmv0[8], pmv1[8];
        #pragma unroll
        for (int nt = 0; nt < 8; nt++) {
            pmv0[nt] = *(const float2*)(pmr0 + kt * 64 + nt * 8);
            pmv1[nt] = *(const float2*)(pmr1 + kt * 64 + nt * 8);
        }

        float acc[8][4];
        #pragma unroll
        for (int j = 0; j < 8; j++)
            #pragma unroll
            for (int k = 0; k < 4; k++) acc[j][k] = 0.f;

        // ---- S = Q*K ----
        #pragma unroll
        for (int ks = 0; ks < 4; ks++) {
            uint32_t ah[4];
            int achk = ((ks * 2 + lhalf) ^ (arow & 7)) * 16;
            ldsm4(ah[0], ah[1], ah[2], ah[3], base + AS_Q + arow * 128 + achk);
            #pragma unroll
            for (int nj = 0; nj < 4; nj++) {
                int brow = nj * 16 + lrow;
                int bchk = ((ks * 2 + lhalf) ^ (brow & 7)) * 16;
                uint32_t kh0, kh1, kh2, kh3;
                ldsm4(kh0, kh1, kh2, kh3, bK + brow * 128 + bchk);
                mma_f16(acc[nj * 2],     ah, kh0, kh2);
                mma_f16(acc[nj * 2 + 1], ah, kh1, kh3);
            }
        }

        // ---- bias + clip + online softmax (log2 domain) ----
        float mx0 = -1e30f, mx1 = -1e30f;
        #pragma unroll
        for (int nt = 0; nt < 8; nt++) {
            float L;
            L = fmaf(lam2, pmv0[nt].x, acc[nt][0] * sc2);
            if (doclip && L < thr0) L = -1e30f;
            acc[nt][0] = L; mx0 = fmaxf(mx0, L);
            L = fmaf(lam2, pmv0[nt].y, acc[nt][1] * sc2);
            if (doclip && L < thr0) L = -1e30f;
            acc[nt][1] = L; mx0 = fmaxf(mx0, L);
            L = fmaf(lam2, pmv1[nt].x, acc[nt][2] * sc2);
            if (doclip && L < thr1) L = -1e30f;
            acc[nt][2] = L; mx1 = fmaxf(mx1, L);
            L = fmaf(lam2, pmv1[nt].y, acc[nt][3] * sc2);
            if (doclip && L < thr1) L = -1e30f;
            acc[nt][3] = L; mx1 = fmaxf(mx1, L);
        }
        mx0 = fmaxf(mx0, __shfl_xor_sync(0xffffffffu, mx0, 1));
        mx0 = fmaxf(mx0, __shfl_xor_sync(0xffffffffu, mx0, 2));
        mx1 = fmaxf(mx1, __shfl_xor_sync(0xffffffffu, mx1, 1));
        mx1 = fmaxf(mx1, __shfl_xor_sync(0xffffffffu, mx1, 2));
        float mn0 = fmaxf(m0, mx0), mn1 = fmaxf(m1, mx1);
        float rs0 = ex2(m0 - mn0), rs1 = ex2(m1 - mn1);
        float s0 = 0.f, s1 = 0.f;
        #pragma unroll
        for (int nt = 0; nt < 8; nt++) {
            float p;
            p = ex2(acc[nt][0] - mn0); acc[nt][0] = p; s0 += p;
            p = ex2(acc[nt][1] - mn0); acc[nt][1] = p; s0 += p;
            p = ex2(acc[nt][2] - mn1); acc[nt][2] = p; s1 += p;
            p = ex2(acc[nt][3] - mn1); acc[nt][3] = p; s1 += p;
        }
        s0 += __shfl_xor_sync(0xffffffffu, s0, 1);
        s0 += __shfl_xor_sync(0xffffffffu, s0, 2);
        s1 += __shfl_xor_sync(0xffffffffu, s1, 1);
        s1 += __shfl_xor_sync(0xffffffffu, s1, 2);
        l0 = fmaf(l0, rs0, s0); m0 = mn0;
        l1 = fmaf(l1, rs1, s1); m1 = mn1;
        #pragma unroll
        for (int nt = 0; nt < 8; nt++) {
            oacc[nt][0] *= rs0; oacc[nt][1] *= rs0;
            oacc[nt][2] *= rs1; oacc[nt][3] *= rs1;
        }

        // ---- O += P*V  (V [s][d] via ldmatrix.trans) ----
        #pragma unroll
        for (int ks = 0; ks < 4; ks++) {
            const int na = 2 * ks, nb2 = 2 * ks + 1;
            uint32_t aph[4];
            aph[0] = pk_f16(acc[na][0],  acc[na][1]);
            aph[1] = pk_f16(acc[na][2],  acc[na][3]);
            aph[2] = pk_f16(acc[nb2][0], acc[nb2][1]);
            aph[3] = pk_f16(acc[nb2][2], acc[nb2][3]);
            const int krow = ks * 16 + vkrow;          // s-row in V tile
            #pragma unroll
            for (int nj = 0; nj < 4; nj++) {
                int chunk = (((nj << 1) + vcolh) ^ (krow & 7)) * 16;
                uint32_t v0, v1, v2, v3;
                ldsm4t(v0, v1, v2, v3, bV + krow * 128 + chunk);
                mma_f16(oacc[nj * 2],     aph, v0, v2);
                mma_f16(oacc[nj * 2 + 1], aph, v1, v3);
            }
        }
    }

    // ---- epilogue: normalize and write fp16 O into A2 ----
    const float inv0 = 1.0f / l0, inv1 = 1.0f / l1;
    const size_t row0 = (size_t)(b * S_) + qt * 128 + w * 16 + tr;
    #pragma unroll
    for (int nt = 0; nt < 8; nt++) {
        int col = h * HD_ + nt * 8 + tc;
        #pragma unroll
        for (int rr = 0; rr < 2; rr++) {
            float v0 = oacc[nt][rr * 2 + 0] * (rr ? inv1 : inv0);
            float v1 = oacc[nt][rr * 2 + 1] * (rr ? inv1 : inv0);
            __half2 hp = {__float2half_rn(v0), __float2half_rn(v1)};
            *(__half2*)(A2out + (row0 + rr * 8) * D_ + col) = hp;
        }
    }
}

// ---------------- launch ------------------------------------------------------
extern "C" void kernel_launch(void* const* d_in, const int* in_sizes, int n_in,
                              void* d_out, int out_size)
{
    const float* x  = (const float*)d_in[0];
    const float* pm = (const float*)d_in[1];
    const float* dx = (const float*)d_in[2];
    const float* wq = (const float*)d_in[3];
    const float* bq = (const float*)d_in[4];
    const float* wk = (const float*)d_in[5];
    const float* bk = (const float*)d_in[6];
    const float* wv = (const float*)d_in[7];
    const float* bv = (const float*)d_in[8];
    const float* wo = (const float*)d_in[9];
    const float* bo = (const float*)d_in[10];
    float* out = (float*)d_out;

    __half *gA2, *gW2;
    cudaGetSymbolAddress((void**)&gA2, g_A2);
    cudaGetSymbolAddress((void**)&gW2, g_W2);

    cudaFuncSetAttribute(gemm_mma<0>, cudaFuncAttributeMaxDynamicSharedMemorySize, GT_TOT);
    cudaFuncSetAttribute(gemm_mma<1>, cudaFuncAttributeMaxDynamicSharedMemorySize, GT_TOT);
    cudaFuncSetAttribute(attn_mma, cudaFuncAttributeMaxDynamicSharedMemorySize, AS_TOT);

    // fused prologue: fp16 converts + row_u + pmrm, then lam
    prologue<<<M_ + 4 * D_ + S_, 256>>>(x, dx, pm, wq, wk, wv, wo);
    lam_kernel<<<B_, 256>>>();

    // fused QKV projection: single GEMM, N = 3072 (q|k|v stacked), K = 1024
    dim3 gqkv(3 * D_ / 128, M_ / 128);
    gemm_mma<1><<<gqkv, 256, GT_TOT>>>(gA2, gW2, bq, bk, bv, nullptr);

    // HMMA flash attention -> writes fp16 O into A2
    dim3 ag(S_ / 128, H_, B_);
    attn_mma<<<ag, 256, AS_TOT>>>(pm, gA2);

    // output projection (K = 1024)
    dim3 go(D_ / 128, M_ / 128);
    gemm_mma<0><<<go, 256, GT_TOT>>>(gA2, gW2 + 3 * (size_t)D_ * D_, bo, bo, bo, out);
}